// round 9
// baseline (speedup 1.0000x reference)
#include <cuda_runtime.h>
#include <math_constants.h>
#include <cstdint>

// Problem constants (fixed by setup_inputs)
#define BB 8
#define NN 2048
#define MM 2048
#define DD 256
#define KSIM 16
#define KCOOR 4
#define NCAND 32

// ---------------- device scratch (allocation-free) ----------------
__device__ float g_f1n[(size_t)BB * NN * DD];
__device__ float g_f2n[(size_t)BB * MM * DD];
__device__ float g_w[(size_t)BB * MM * NN];   // approx (tf32) exp(w1)
__device__ float g_den1[(size_t)BB * NN];
__device__ float g_den2[(size_t)BB * MM];

// ---------------- accurate-class expf replica (XLA:CPU / Eigen / Cephes) ----------------
__device__ __forceinline__ float xla_expf(float x) {
    const float exp_hi = 88.3762626647950f;
    const float exp_lo = -88.3762626647949f;
    const float LOG2EF = 1.44269504088896341f;
    const float C1     = 0.693359375f;
    const float C2     = -2.12194440e-4f;
    const float p0     = 1.9875691500e-4f;
    const float p1     = 1.3981999507e-3f;
    const float p2     = 8.3334519073e-3f;
    const float p3     = 4.1665795894e-2f;
    const float p4     = 1.6666665459e-1f;
    const float p5     = 5.0000001201e-1f;

    x = fminf(x, exp_hi);
    x = fmaxf(x, exp_lo);

    float fx = floorf(fmaf(x, LOG2EF, 0.5f));

    float tmp = __fmul_rn(C1, fx);
    float z   = __fmul_rn(C2, fx);
    float r   = __fsub_rn(x, tmp);
    r = __fsub_rn(r, z);

    float r2 = __fmul_rn(r, r);

    float y = p0;
    y = fmaf(y, r, p1);
    y = fmaf(y, r, p2);
    y = fmaf(y, r, p3);
    y = fmaf(y, r, p4);
    y = fmaf(y, r, p5);
    y = fmaf(y, r2, r);
    y = __fadd_rn(y, 1.0f);

    int n = (int)fx;
    float pow2n = __int_as_float((n + 127) << 23);
    return __fmul_rn(y, pow2n);
}

// ---------------- helpers ----------------
__device__ __forceinline__ void amx(float& bv, int& bi, float v2, int i2) {
    if (v2 > bv || (v2 == bv && i2 < bi)) { bv = v2; bi = i2; }
}
__device__ __forceinline__ unsigned f2tf32(float f) {
    unsigned u;
    asm("cvt.rna.tf32.f32 %0, %1;" : "=r"(u) : "f"(f));
    return u;
}

// ---------------- kernel 1a: per-row norms, XLA:CPU sharded-vector reduce replica ----
__global__ void row_norms(const float* __restrict__ in, float* __restrict__ den, int rows) {
    int r = blockIdx.x * blockDim.x + threadIdx.x;
    if (r >= rows) return;
    const float* v = in + (size_t)r * DD;

    float s[16];
    #pragma unroll
    for (int l = 0; l < 16; l++) s[l] = 0.f;

    for (int t = 0; t < DD; t += 16) {
        #pragma unroll
        for (int l = 0; l < 16; l++) {
            float x = v[t + l];
            s[l] = __fadd_rn(s[l], __fmul_rn(x, x));
        }
    }
    float V[4];
    #pragma unroll
    for (int l = 0; l < 4; l++)
        V[l] = __fadd_rn(__fadd_rn(s[l], s[4 + l]), __fadd_rn(s[8 + l], s[12 + l]));
    float total = __fadd_rn(__fadd_rn(V[0], V[2]), __fadd_rn(V[1], V[3]));
    den[r] = fmaxf(sqrtf(total), 1e-8f);
}

// ---------------- kernel 1b: elementwise divide ----------------
__global__ void div_rows(const float* __restrict__ in, const float* __restrict__ den,
                         float* __restrict__ out) {
    int row = blockIdx.x;
    float d = den[row];
    out[(size_t)row * DD + threadIdx.x] = __fdiv_rn(in[(size_t)row * DD + threadIdx.x], d);
}

// ---------------- kernel 2: tf32 mma.sync batched NT-GEMM, xla-exp epilogue ----------------
// C[b][m][n] = xla_expf( f2n[b][m] . f1n[b][n] )  (approximate: tf32 inputs)
#define TBM 128
#define TBN 128
#define TBK 32
#define KPAD 36
__global__ __launch_bounds__(256)
void gemm_tf32_exp(const float* __restrict__ A, const float* __restrict__ Bm,
                   float* __restrict__ C) {
    __shared__ unsigned As[TBM][KPAD];
    __shared__ unsigned Bs[TBN][KPAD];

    const int b  = blockIdx.z;
    const int bm = blockIdx.y * TBM;
    const int bn = blockIdx.x * TBN;
    const float* Ab = A  + (size_t)b * MM * DD;
    const float* Bb = Bm + (size_t)b * NN * DD;
    float*       Cb = C  + (size_t)b * MM * NN;

    const int tid  = threadIdx.x;
    const int warp = tid >> 5;
    const int lane = tid & 31;
    const int wm   = (warp & 1) * 64;    // warp row offset (2 warps over M)
    const int wn   = (warp >> 1) * 32;   // warp col offset (4 warps over N)
    const int gid  = lane >> 2;          // 0..7
    const int thr  = lane & 3;           // 0..3

    // loader mapping: 2 threads per row, 16 floats each
    const int lrow = tid >> 1;
    const int lk   = (tid & 1) * 16;

    float acc[4][4][4];
    #pragma unroll
    for (int i = 0; i < 4; i++)
        #pragma unroll
        for (int j = 0; j < 4; j++)
            #pragma unroll
            for (int c = 0; c < 4; c++) acc[i][j][c] = 0.f;

    float4 ra[4], rb[4];
    const float* aptr = Ab + (size_t)(bm + lrow) * DD + lk;
    const float* bptr = Bb + (size_t)(bn + lrow) * DD + lk;
    #pragma unroll
    for (int i = 0; i < 4; i++) {
        ra[i] = *(const float4*)(aptr + i * 4);
        rb[i] = *(const float4*)(bptr + i * 4);
    }

    for (int it = 0; it < DD / TBK; it++) {
        // store staged regs to smem (convert to tf32 bits)
        #pragma unroll
        for (int i = 0; i < 4; i++) {
            uint4 ua, ub;
            ua.x = f2tf32(ra[i].x); ua.y = f2tf32(ra[i].y);
            ua.z = f2tf32(ra[i].z); ua.w = f2tf32(ra[i].w);
            ub.x = f2tf32(rb[i].x); ub.y = f2tf32(rb[i].y);
            ub.z = f2tf32(rb[i].z); ub.w = f2tf32(rb[i].w);
            *(uint4*)&As[lrow][lk + i * 4] = ua;
            *(uint4*)&Bs[lrow][lk + i * 4] = ub;
        }
        __syncthreads();

        if (it + 1 < DD / TBK) {
            const float* ap = aptr + (it + 1) * TBK;
            const float* bp = bptr + (it + 1) * TBK;
            #pragma unroll
            for (int i = 0; i < 4; i++) {
                ra[i] = *(const float4*)(ap + i * 4);
                rb[i] = *(const float4*)(bp + i * 4);
            }
        }

        // 4 k-steps of 8
        #pragma unroll
        for (int ks = 0; ks < 4; ks++) {
            const int kb = ks * 8;
            unsigned a0[4], a1[4], a2[4], a3[4], b0[4], b1[4];
            #pragma unroll
            for (int mf = 0; mf < 4; mf++) {
                const int r0 = wm + mf * 16 + gid;
                a0[mf] = As[r0][kb + thr];
                a1[mf] = As[r0 + 8][kb + thr];
                a2[mf] = As[r0][kb + thr + 4];
                a3[mf] = As[r0 + 8][kb + thr + 4];
            }
            #pragma unroll
            for (int nf = 0; nf < 4; nf++) {
                const int c0 = wn + nf * 8 + gid;
                b0[nf] = Bs[c0][kb + thr];
                b1[nf] = Bs[c0][kb + thr + 4];
            }
            #pragma unroll
            for (int mf = 0; mf < 4; mf++)
                #pragma unroll
                for (int nf = 0; nf < 4; nf++) {
                    asm volatile(
                        "mma.sync.aligned.m16n8k8.row.col.f32.tf32.tf32.f32 "
                        "{%0,%1,%2,%3}, {%4,%5,%6,%7}, {%8,%9}, {%0,%1,%2,%3};"
                        : "+f"(acc[mf][nf][0]), "+f"(acc[mf][nf][1]),
                          "+f"(acc[mf][nf][2]), "+f"(acc[mf][nf][3])
                        : "r"(a0[mf]), "r"(a1[mf]), "r"(a2[mf]), "r"(a3[mf]),
                          "r"(b0[nf]), "r"(b1[nf]));
                }
        }
        __syncthreads();
    }

    // epilogue: apply xla_expf, write
    #pragma unroll
    for (int mf = 0; mf < 4; mf++) {
        const int row = bm + wm + mf * 16 + gid;
        #pragma unroll
        for (int nf = 0; nf < 4; nf++) {
            const int col = bn + wn + nf * 8 + thr * 2;
            float2 v0, v1;
            v0.x = xla_expf(acc[mf][nf][0]);
            v0.y = xla_expf(acc[mf][nf][1]);
            v1.x = xla_expf(acc[mf][nf][2]);
            v1.y = xla_expf(acc[mf][nf][3]);
            *(float2*)&Cb[(size_t)row * NN + col]       = v0;
            *(float2*)&Cb[(size_t)(row + 8) * NN + col] = v1;
        }
    }
}

// ---------------- kernel 3: fused row kernel (approx window + exact re-rank) ----------------
__global__ __launch_bounds__(256)
void row_topk(const float* __restrict__ w_in, const float* __restrict__ f1,
              const float* __restrict__ f1n, const float* __restrict__ f2n,
              const float* __restrict__ p, const float* __restrict__ q,
              float* __restrict__ f_out, float* __restrict__ idx_out,
              float* __restrict__ w_out) {
    const int m = blockIdx.x;
    const int b = blockIdx.y;
    const int tid  = threadIdx.x;   // 256
    const int lane = tid & 31;
    const int wid  = tid >> 5;

    __shared__ float ws[NN];
    __shared__ float w2s[NN];
    __shared__ float f2row[DD];
    __shared__ float sv[8];
    __shared__ int   si[8];
    __shared__ int   b4i[KCOOR];
    __shared__ float b4v[KCOOR];
    __shared__ int   cand[NCAND];
    __shared__ float keyf[NCAND];
    __shared__ int   sel[KSIM];

    const size_t rowbase = ((size_t)b * MM + m) * NN;

    for (int n = tid; n < NN; n += 256) ws[n] = w_in[rowbase + n];
    if (tid < DD) f2row[tid] = f2n[((size_t)b * MM + m) * DD + tid];

    // exact w2 row (bit recipe unchanged)
    const float qx = q[((size_t)b * MM + m) * 3 + 0];
    const float qy = q[((size_t)b * MM + m) * 3 + 1];
    const float qz = q[((size_t)b * MM + m) * 3 + 2];
    const float qq = __fadd_rn(__fadd_rn(__fmul_rn(qx, qx), __fmul_rn(qy, qy)),
                               __fmul_rn(qz, qz));
    for (int n = tid; n < NN; n += 256) {
        const float px = p[((size_t)b * NN + n) * 3 + 0];
        const float py = p[((size_t)b * NN + n) * 3 + 1];
        const float pz = p[((size_t)b * NN + n) * 3 + 2];
        const float pp = __fadd_rn(__fadd_rn(__fmul_rn(px, px), __fmul_rn(py, py)),
                                   __fmul_rn(pz, pz));
        const float dot3 = fmaf(qz, pz, fmaf(qy, py, __fmul_rn(qx, px)));
        const float d2 = __fsub_rn(__fadd_rn(qq, pp), __fmul_rn(2.0f, dot3));
        w2s[n] = xla_expf(-d2);
    }
    __syncthreads();

    // exact top-4 of w2 (tie -> smaller index); record boosts, add into approx ws
    for (int t = 0; t < KCOOR; t++) {
        float bv = -CUDART_INF_F; int bi = 1 << 30;
        for (int n = tid; n < NN; n += 256) amx(bv, bi, w2s[n], n);
        #pragma unroll
        for (int o = 16; o > 0; o >>= 1) {
            float v2 = __shfl_xor_sync(0xffffffffu, bv, o);
            int   i2 = __shfl_xor_sync(0xffffffffu, bi, o);
            amx(bv, bi, v2, i2);
        }
        if (lane == 0) { sv[wid] = bv; si[wid] = bi; }
        __syncthreads();
        if (tid == 0) {
            float fv = sv[0]; int fi = si[0];
            #pragma unroll
            for (int i = 1; i < 8; i++) amx(fv, fi, sv[i], si[i]);
            b4i[t] = fi; b4v[t] = fv;
            ws[fi] = __fadd_rn(ws[fi], fv);
            w2s[fi] = -CUDART_INF_F;
        }
        __syncthreads();
    }

    if (w_out) {
        for (int n = tid; n < NN; n += 256) w_out[rowbase + n] = ws[n];
        __syncthreads();
    }

    // approx top-NCAND window (destructive)
    for (int t = 0; t < NCAND; t++) {
        float bv = -CUDART_INF_F; int bi = 1 << 30;
        for (int n = tid; n < NN; n += 256) amx(bv, bi, ws[n], n);
        #pragma unroll
        for (int o = 16; o > 0; o >>= 1) {
            float v2 = __shfl_xor_sync(0xffffffffu, bv, o);
            int   i2 = __shfl_xor_sync(0xffffffffu, bi, o);
            amx(bv, bi, v2, i2);
        }
        if (lane == 0) { sv[wid] = bv; si[wid] = bi; }
        __syncthreads();
        if (tid == 0) {
            float fv = sv[0]; int fi = si[0];
            #pragma unroll
            for (int i = 1; i < 8; i++) amx(fv, fi, sv[i], si[i]);
            cand[t] = fi;
            ws[fi] = -CUDART_INF_F;
        }
        __syncthreads();
    }

    // exact keys for the window: sequential fmaf chain (frozen bit recipe) + accurate exp
    if (tid < NCAND) {
        const int n = cand[tid];
        const float* f1r = f1n + ((size_t)b * NN + n) * DD;
        float acc = 0.f;
        for (int k = 0; k < DD; k++)
            acc = fmaf(f2row[k], f1r[k], acc);
        keyf[tid] = xla_expf(acc);
    }
    __syncthreads();

    // exact boosts + stable exact top-16 (desc, tie -> smaller index)
    if (tid == 0) {
        #pragma unroll
        for (int t = 0; t < KCOOR; t++) {
            for (int c = 0; c < NCAND; c++) {
                if (cand[c] == b4i[t]) {
                    keyf[c] = __fadd_rn(keyf[c], b4v[t]);
                    break;
                }
            }
        }
        bool used[NCAND] = {false};
        for (int t = 0; t < KSIM; t++) {
            int best = -1;
            for (int c = 0; c < NCAND; c++) {
                if (used[c]) continue;
                if (best < 0 || keyf[c] > keyf[best] ||
                    (keyf[c] == keyf[best] && cand[c] < cand[best])) best = c;
            }
            used[best] = true;
            sel[t] = cand[best];
        }
    }
    __syncthreads();

    if (idx_out && tid < KSIM)
        idx_out[((size_t)b * MM + m) * KSIM + tid] = (float)sel[tid];

    if (f_out) {
        const int d = tid;   // DD == 256 == blockDim
        float s = 0.f, mx = -CUDART_INF_F;
        #pragma unroll
        for (int k = 0; k < KSIM; k++) {
            float v = f1[((size_t)b * NN + sel[k]) * DD + d];
            s += v;
            mx = fmaxf(mx, v);
        }
        size_t fo = ((size_t)b * MM + m) * (2 * DD);
        f_out[fo + d]      = s * (1.0f / 16.0f);
        f_out[fo + DD + d] = mx;
    }
}

// ---------------- launch ----------------
extern "C" void kernel_launch(void* const* d_in, const int* in_sizes, int n_in,
                              void* d_out, int out_size) {
    const float* f1 = (const float*)d_in[0];
    const float* f2 = (const float*)d_in[1];
    const float* p  = (const float*)d_in[2];
    const float* q  = (const float*)d_in[3];

    float* f1n;  cudaGetSymbolAddress((void**)&f1n,  g_f1n);
    float* f2n;  cudaGetSymbolAddress((void**)&f2n,  g_f2n);
    float* wbuf; cudaGetSymbolAddress((void**)&wbuf, g_w);
    float* den1; cudaGetSymbolAddress((void**)&den1, g_den1);
    float* den2; cudaGetSymbolAddress((void**)&den2, g_den2);

    const size_t F_E = (size_t)BB * MM * (2 * DD);
    const size_t I_E = (size_t)BB * MM * KSIM;
    const size_t W_E = (size_t)BB * MM * NN;

    float* out = (float*)d_out;
    float* f_out = nullptr; float* idx_out = nullptr; float* w_out = nullptr;
    size_t osz = (size_t)out_size;
    if (osz >= F_E + I_E + W_E) {
        f_out = out; idx_out = out + F_E; w_out = out + F_E + I_E;
    } else if (osz == F_E + I_E) {
        f_out = out; idx_out = out + F_E;
    } else if (osz == W_E) {
        w_out = out;
    } else {
        f_out = out;
    }

    row_norms<<<(BB * NN + 255) / 256, 256>>>(f1, den1, BB * NN);
    row_norms<<<(BB * MM + 255) / 256, 256>>>(f2, den2, BB * MM);
    div_rows<<<BB * NN, 256>>>(f1, den1, f1n);
    div_rows<<<BB * MM, 256>>>(f2, den2, f2n);

    dim3 ggrid(NN / TBN, MM / TBM, BB);
    gemm_tf32_exp<<<ggrid, 256>>>(f2n, f1n, wbuf);

    dim3 rgrid(MM, BB);
    row_topk<<<rgrid, 256>>>(wbuf, f1, f1n, f2n, p, q, f_out, idx_out, w_out);
}